// round 1
// baseline (speedup 1.0000x reference)
#include <cuda_runtime.h>
#include <math.h>

#define L_  6
#define H_  8
#define D_  512
#define F_  2048
#define S_  512
#define V_  50257
#define B_  8
#define HD_ 64
#define N_TOK (B_*S_)                      // 4096
#define NLOGITS ((long long)N_TOK * V_)    // 205852672

// ---------------- scratch (static device globals; no allocation) ----------------
__device__ float g_h  [N_TOK*D_];
__device__ float g_xn [N_TOK*D_];
__device__ float g_q  [N_TOK*D_];
__device__ float g_k  [N_TOK*D_];
__device__ float g_v  [N_TOK*D_];
__device__ float g_ctx[N_TOK*D_];
__device__ float g_ff [N_TOK*F_];
__device__ float g_loss[N_TOK];
__device__ int   g_is64;

// ---------------- int32/int64 token-id detection ----------------
// If ids are int64 (values < 2^31), every odd 32-bit word of the buffer is 0.
// If int32, buffer holds 4096 random ids in [0, 50257) -> essentially impossible
// for 2048 odd words to all be zero. Reads stay within 4096 int32s either way.
__global__ void detect_kernel(const int* __restrict__ xr) {
    __shared__ int ok;
    if (threadIdx.x == 0) ok = 1;
    __syncthreads();
    for (int i = threadIdx.x; i < N_TOK/2; i += blockDim.x)
        if (xr[2*i + 1] != 0) ok = 0;
    __syncthreads();
    if (threadIdx.x == 0) g_is64 = ok;
}

__device__ __forceinline__ int get_tok(const void* p, int i) {
    return g_is64 ? (int)((const long long*)p)[i] : ((const int*)p)[i];
}

// ---------------- embedding: h = token_emb[x] + pos_emb[s] ----------------
__global__ void embed_kernel(const void* __restrict__ x,
                             const float* __restrict__ temb,
                             const float* __restrict__ pemb) {
    int n = blockIdx.x;
    int tok = get_tok(x, n);
    int s = n % S_;
    const float4* te = (const float4*)(temb + (size_t)tok * D_);
    const float4* pe = (const float4*)(pemb + (size_t)s   * D_);
    float4* out = (float4*)(g_h + (size_t)n * D_);
    int t = threadIdx.x;                    // 128 threads, 128 float4
    float4 a = te[t], b = pe[t];
    out[t] = make_float4(a.x+b.x, a.y+b.y, a.z+b.z, a.w+b.w);
}

// ---------------- layernorm: block per token, 128 threads ----------------
__global__ void layernorm_kernel(const float* __restrict__ in,
                                 const float* __restrict__ g,
                                 const float* __restrict__ b,
                                 float* __restrict__ out) {
    int n = blockIdx.x;
    int t = threadIdx.x;                    // 0..127
    float4 v = ((const float4*)(in + (size_t)n * D_))[t];
    float s  = v.x + v.y + v.z + v.w;
    float ss = v.x*v.x + v.y*v.y + v.z*v.z + v.w*v.w;
    #pragma unroll
    for (int o = 16; o > 0; o >>= 1) {
        s  += __shfl_down_sync(0xffffffffu, s,  o);
        ss += __shfl_down_sync(0xffffffffu, ss, o);
    }
    __shared__ float rs[4], rss[4];
    __shared__ float mu_s, rstd_s;
    int w = t >> 5, lane = t & 31;
    if (lane == 0) { rs[w] = s; rss[w] = ss; }
    __syncthreads();
    if (t == 0) {
        float S1 = 0.f, S2 = 0.f;
        #pragma unroll
        for (int i = 0; i < 4; i++) { S1 += rs[i]; S2 += rss[i]; }
        float mu = S1 / D_;
        mu_s = mu;
        rstd_s = rsqrtf(S2 / D_ - mu*mu + 1e-5f);
    }
    __syncthreads();
    float mu = mu_s, r = rstd_s;
    float4 gg = ((const float4*)g)[t];
    float4 bb = ((const float4*)b)[t];
    float4 o;
    o.x = (v.x - mu) * r * gg.x + bb.x;
    o.y = (v.y - mu) * r * gg.y + bb.y;
    o.z = (v.z - mu) * r * gg.z + bb.z;
    o.w = (v.w - mu) * r * gg.w + bb.w;
    ((float4*)(out + (size_t)n * D_))[t] = o;
}

// ---------------- SGEMM 128x128, K-tile 8, 8x8 per thread ----------------
// C[M,N] = epilogue(A[M,K] @ B)  ; B is [K,N] (NN) or [N,K] (NT, TRANSB).
// epilogue: +bias (if bias), gelu-exact (if act), +res (if res).
template<bool TRANSB>
__global__ void __launch_bounds__(256)
sgemm_kernel(const float* __restrict__ A, const float* __restrict__ Bm,
             const float* __restrict__ bias, const float* __restrict__ res,
             float* __restrict__ C, int M, int N, int K, int act) {
    __shared__ float As[8][128];
    __shared__ float Bs[8][132];
    int tid = threadIdx.x;
    int tr = tid >> 4, tc = tid & 15;
    int row0 = blockIdx.y * 128;
    int col0 = blockIdx.x * 128;
    float acc[8][8];
    #pragma unroll
    for (int i = 0; i < 8; i++)
        #pragma unroll
        for (int j = 0; j < 8; j++) acc[i][j] = 0.f;

    int ar = tid >> 1, ac = (tid & 1) * 4;
    for (int k0 = 0; k0 < K; k0 += 8) {
        float4 a4 = *(const float4*)(A + (size_t)(row0 + ar) * K + k0 + ac);
        As[ac+0][ar] = a4.x; As[ac+1][ar] = a4.y;
        As[ac+2][ar] = a4.z; As[ac+3][ar] = a4.w;
        if (!TRANSB) {
            int br = tid >> 5, bc = (tid & 31) * 4;
            float4 b4 = *(const float4*)(Bm + (size_t)(k0 + br) * N + col0 + bc);
            Bs[br][bc+0] = b4.x; Bs[br][bc+1] = b4.y;
            Bs[br][bc+2] = b4.z; Bs[br][bc+3] = b4.w;
        } else {
            int bn = tid >> 1, bk = (tid & 1) * 4;
            float4 b4 = make_float4(0.f, 0.f, 0.f, 0.f);
            if (col0 + bn < N)
                b4 = *(const float4*)(Bm + (size_t)(col0 + bn) * K + k0 + bk);
            Bs[bk+0][bn] = b4.x; Bs[bk+1][bn] = b4.y;
            Bs[bk+2][bn] = b4.z; Bs[bk+3][bn] = b4.w;
        }
        __syncthreads();
        #pragma unroll
        for (int kk = 0; kk < 8; kk++) {
            float ra[8], rb[8];
            #pragma unroll
            for (int i = 0; i < 8; i++) ra[i] = As[kk][tr*8 + i];
            #pragma unroll
            for (int j = 0; j < 8; j++) rb[j] = Bs[kk][tc*8 + j];
            #pragma unroll
            for (int i = 0; i < 8; i++)
                #pragma unroll
                for (int j = 0; j < 8; j++)
                    acc[i][j] = fmaf(ra[i], rb[j], acc[i][j]);
        }
        __syncthreads();
    }
    #pragma unroll
    for (int i = 0; i < 8; i++) {
        int r = row0 + tr*8 + i;
        if (r >= M) continue;
        #pragma unroll
        for (int j = 0; j < 8; j++) {
            int c = col0 + tc*8 + j;
            if (c < N) {
                float x = acc[i][j];
                if (bias) x += bias[c];
                if (act)  x = 0.5f * x * (1.0f + erff(x * 0.70710678118654752f));
                if (res)  x += res[(size_t)r * N + c];
                C[(size_t)r * N + c] = x;
            }
        }
    }
}

// ---------------- fused causal attention: one block per (query row, b*h) ----------
__global__ void attention_kernel(const float* __restrict__ q,
                                 const float* __restrict__ k,
                                 const float* __restrict__ v,
                                 float* __restrict__ ctx) {
    int i  = blockIdx.x;
    int bh = blockIdx.y;
    int b  = bh / H_, h = bh % H_;
    int t  = threadIdx.x;                   // 128
    __shared__ float sq[HD_];
    __shared__ float sc[S_];
    __shared__ float red[128];

    const float* qrow = q + ((size_t)(b*S_ + i)) * D_ + h * HD_;
    if (t < HD_) sq[t] = qrow[t];
    __syncthreads();

    float lmax = -1e30f;
    for (int j = t; j <= i; j += 128) {
        const float* kr = k + ((size_t)(b*S_ + j)) * D_ + h * HD_;
        float dot = 0.f;
        #pragma unroll
        for (int d = 0; d < HD_; d++) dot = fmaf(sq[d], kr[d], dot);
        dot *= 0.125f;                      // 1/sqrt(64)
        sc[j] = dot;
        lmax = fmaxf(lmax, dot);
    }
    red[t] = lmax; __syncthreads();
    #pragma unroll
    for (int o = 64; o > 0; o >>= 1) {
        if (t < o) red[t] = fmaxf(red[t], red[t + o]);
        __syncthreads();
    }
    float m = red[0];
    __syncthreads();

    float lsum = 0.f;
    for (int j = t; j <= i; j += 128) {
        float e = expf(sc[j] - m);
        sc[j] = e;
        lsum += e;
    }
    red[t] = lsum; __syncthreads();
    #pragma unroll
    for (int o = 64; o > 0; o >>= 1) {
        if (t < o) red[t] += red[t + o];
        __syncthreads();
    }
    float rinv = 1.f / red[0];
    __syncthreads();

    if (t < HD_) {
        float acc = 0.f;
        const float* vb = v + (size_t)(b*S_) * D_ + h * HD_ + t;
        for (int j = 0; j <= i; j++)
            acc = fmaf(sc[j], vb[(size_t)j * D_], acc);
        ctx[((size_t)(b*S_ + i)) * D_ + h * HD_ + t] = acc * rinv;
    }
}

// ---------------- loss: per-token log-softmax NLL, then mean ----------------
__global__ void loss_kernel(const float* __restrict__ logits,
                            const void* __restrict__ tgt) {
    int n = blockIdx.x;
    const float* row = logits + (size_t)n * V_;
    int t = threadIdx.x;                    // 256
    __shared__ float red[256];
    float m = -1e30f;
    for (int i = t; i < V_; i += 256) m = fmaxf(m, row[i]);
    red[t] = m; __syncthreads();
    #pragma unroll
    for (int o = 128; o > 0; o >>= 1) {
        if (t < o) red[t] = fmaxf(red[t], red[t + o]);
        __syncthreads();
    }
    m = red[0]; __syncthreads();
    float s = 0.f;
    for (int i = t; i < V_; i += 256) s += expf(row[i] - m);
    red[t] = s; __syncthreads();
    #pragma unroll
    for (int o = 128; o > 0; o >>= 1) {
        if (t < o) red[t] += red[t + o];
        __syncthreads();
    }
    if (t == 0) {
        int tg = get_tok(tgt, n);
        g_loss[n] = m + logf(red[0]) - row[tg];
    }
}

__global__ void loss_reduce_kernel(float* __restrict__ out, long long out_size) {
    int t = threadIdx.x;
    __shared__ float red[256];
    float s = 0.f;
    for (int i = t; i < N_TOK; i += 256) s += g_loss[i];
    red[t] = s; __syncthreads();
    #pragma unroll
    for (int o = 128; o > 0; o >>= 1) {
        if (t < o) red[t] += red[t + o];
        __syncthreads();
    }
    if (t == 0) {
        float mean = red[0] / (float)N_TOK;
        if (out_size > NLOGITS)      out[NLOGITS] = mean;  // logits then loss
        else if (out_size == 1)      out[0]       = mean;  // loss only
    }
}

// ---------------- host side ----------------
static void gemm(const float* A, const float* Bm, const float* bias, const float* res,
                 float* C, int M, int N, int K, int act, bool transB) {
    dim3 grid((N + 127) / 128, (M + 127) / 128);
    if (transB) sgemm_kernel<true ><<<grid, 256>>>(A, Bm, bias, res, C, M, N, K, act);
    else        sgemm_kernel<false><<<grid, 256>>>(A, Bm, bias, res, C, M, N, K, act);
}

extern "C" void kernel_launch(void* const* d_in, const int* in_sizes, int n_in,
                              void* d_out, int out_size) {
    const void*  x       = d_in[0];
    const void*  targets = d_in[1];
    const float* temb    = (const float*)d_in[2];
    const float* pemb    = (const float*)d_in[3];
    const float* ln1_g   = (const float*)d_in[4];
    const float* ln1_b   = (const float*)d_in[5];
    const float* Wq      = (const float*)d_in[6];
    const float* bq      = (const float*)d_in[7];
    const float* Wk      = (const float*)d_in[8];
    const float* bk      = (const float*)d_in[9];
    const float* Wv      = (const float*)d_in[10];
    const float* bv      = (const float*)d_in[11];
    const float* Wo      = (const float*)d_in[12];
    const float* bo      = (const float*)d_in[13];
    const float* ln2_g   = (const float*)d_in[14];
    const float* ln2_b   = (const float*)d_in[15];
    const float* W1      = (const float*)d_in[16];
    const float* b1      = (const float*)d_in[17];
    const float* W2      = (const float*)d_in[18];
    const float* b2      = (const float*)d_in[19];
    const float* lnf_g   = (const float*)d_in[20];
    const float* lnf_b   = (const float*)d_in[21];
    float* out = (float*)d_out;

    float *h, *xn, *q, *k, *v, *ctx, *ff;
    cudaGetSymbolAddress((void**)&h,   g_h);
    cudaGetSymbolAddress((void**)&xn,  g_xn);
    cudaGetSymbolAddress((void**)&q,   g_q);
    cudaGetSymbolAddress((void**)&k,   g_k);
    cudaGetSymbolAddress((void**)&v,   g_v);
    cudaGetSymbolAddress((void**)&ctx, g_ctx);
    cudaGetSymbolAddress((void**)&ff,  g_ff);

    detect_kernel<<<1, 256>>>((const int*)x);
    embed_kernel<<<N_TOK, 128>>>(x, temb, pemb);

    for (int l = 0; l < L_; l++) {
        layernorm_kernel<<<N_TOK, 128>>>(h, ln1_g + (size_t)l*D_, ln1_b + (size_t)l*D_, xn);
        gemm(xn, Wq + (size_t)l*D_*D_, bq + (size_t)l*D_, nullptr, q, N_TOK, D_, D_, 0, false);
        gemm(xn, Wk + (size_t)l*D_*D_, bk + (size_t)l*D_, nullptr, k, N_TOK, D_, D_, 0, false);
        gemm(xn, Wv + (size_t)l*D_*D_, bv + (size_t)l*D_, nullptr, v, N_TOK, D_, D_, 0, false);

        dim3 ag(S_, B_ * H_);
        attention_kernel<<<ag, 128>>>(q, k, v, ctx);

        gemm(ctx, Wo + (size_t)l*D_*D_, bo + (size_t)l*D_, h, h, N_TOK, D_, D_, 0, false);

        layernorm_kernel<<<N_TOK, 128>>>(h, ln2_g + (size_t)l*D_, ln2_b + (size_t)l*D_, xn);
        gemm(xn, W1 + (size_t)l*D_*F_, b1 + (size_t)l*F_, nullptr, ff, N_TOK, F_, D_, 1, false);
        gemm(ff, W2 + (size_t)l*F_*D_, b2 + (size_t)l*D_, h, h, N_TOK, D_, F_, 0, false);
    }

    layernorm_kernel<<<N_TOK, 128>>>(h, lnf_g, lnf_b, xn);
    gemm(xn, temb, nullptr, nullptr, out, N_TOK, V_, D_, 0, true);  // logits = h @ emb^T

    loss_kernel<<<N_TOK, 256>>>(out, targets);
    loss_reduce_kernel<<<1, 256>>>(out, (long long)out_size);
}

// round 2
// speedup vs baseline: 1.4393x; 1.4393x over previous
#include <cuda_runtime.h>
#include <math.h>

#define L_  6
#define H_  8
#define D_  512
#define F_  2048
#define S_  512
#define V_  50257
#define B_  8
#define HD_ 64
#define N_TOK (B_*S_)                      // 4096
#define NLOGITS ((long long)N_TOK * V_)    // 205852672

// ---------------- scratch (static device globals; no allocation) ----------------
__device__ float g_h  [N_TOK*D_];
__device__ float g_xn [N_TOK*D_];
__device__ float g_q  [N_TOK*D_];
__device__ float g_k  [N_TOK*D_];
__device__ float g_v  [N_TOK*D_];
__device__ float g_ctx[N_TOK*D_];
__device__ float g_ff [N_TOK*F_];
__device__ float g_loss[N_TOK];
__device__ int   g_is64;

// ---------------- int32/int64 token-id detection ----------------
__global__ void detect_kernel(const int* __restrict__ xr) {
    __shared__ int ok;
    if (threadIdx.x == 0) ok = 1;
    __syncthreads();
    for (int i = threadIdx.x; i < N_TOK/2; i += blockDim.x)
        if (xr[2*i + 1] != 0) ok = 0;
    __syncthreads();
    if (threadIdx.x == 0) g_is64 = ok;
}

__device__ __forceinline__ int get_tok(const void* p, int i) {
    return g_is64 ? (int)((const long long*)p)[i] : ((const int*)p)[i];
}

// ---------------- embedding ----------------
__global__ void embed_kernel(const void* __restrict__ x,
                             const float* __restrict__ temb,
                             const float* __restrict__ pemb) {
    int n = blockIdx.x;
    int tok = get_tok(x, n);
    int s = n % S_;
    const float4* te = (const float4*)(temb + (size_t)tok * D_);
    const float4* pe = (const float4*)(pemb + (size_t)s   * D_);
    float4* out = (float4*)(g_h + (size_t)n * D_);
    int t = threadIdx.x;
    float4 a = te[t], b = pe[t];
    out[t] = make_float4(a.x+b.x, a.y+b.y, a.z+b.z, a.w+b.w);
}

// ---------------- layernorm ----------------
__global__ void layernorm_kernel(const float* __restrict__ in,
                                 const float* __restrict__ g,
                                 const float* __restrict__ b,
                                 float* __restrict__ out) {
    int n = blockIdx.x;
    int t = threadIdx.x;
    float4 v = ((const float4*)(in + (size_t)n * D_))[t];
    float s  = v.x + v.y + v.z + v.w;
    float ss = v.x*v.x + v.y*v.y + v.z*v.z + v.w*v.w;
    #pragma unroll
    for (int o = 16; o > 0; o >>= 1) {
        s  += __shfl_down_sync(0xffffffffu, s,  o);
        ss += __shfl_down_sync(0xffffffffu, ss, o);
    }
    __shared__ float rs[4], rss[4];
    __shared__ float mu_s, rstd_s;
    int w = t >> 5, lane = t & 31;
    if (lane == 0) { rs[w] = s; rss[w] = ss; }
    __syncthreads();
    if (t == 0) {
        float S1 = 0.f, S2 = 0.f;
        #pragma unroll
        for (int i = 0; i < 4; i++) { S1 += rs[i]; S2 += rss[i]; }
        float mu = S1 / D_;
        mu_s = mu;
        rstd_s = rsqrtf(S2 / D_ - mu*mu + 1e-5f);
    }
    __syncthreads();
    float mu = mu_s, r = rstd_s;
    float4 gg = ((const float4*)g)[t];
    float4 bb = ((const float4*)b)[t];
    float4 o;
    o.x = (v.x - mu) * r * gg.x + bb.x;
    o.y = (v.y - mu) * r * gg.y + bb.y;
    o.z = (v.z - mu) * r * gg.z + bb.z;
    o.w = (v.w - mu) * r * gg.w + bb.w;
    ((float4*)(out + (size_t)n * D_))[t] = o;
}

// ---------------- TF32 tensor-core GEMM ----------------
// C[M,N] = epi(A[M,K] @ B); B [K,N] (NN) or [N,K] (NT).
// 128x128 CTA tile, BK=16, double-buffered smem, 8 warps (2m x 4n), warp 64x32,
// mma.sync.m16n8k8.tf32. A/B converted to tf32 at smem-store; accum fp32.
__device__ __forceinline__ float to_tf32(float x) {
    float r;
    asm("cvt.rna.tf32.f32 %0, %1;" : "=f"(r) : "f"(x));
    return r;
}

template<bool TRANSB>
__global__ void __launch_bounds__(256)
mma_gemm_kernel(const float* __restrict__ A, const float* __restrict__ Bm,
                const float* __restrict__ bias, const float* __restrict__ res,
                float* __restrict__ C, int M, int N, int K, int act)
{
    constexpr int BM = 128, BN = 128, BK = 16, PAD = 8;
    __shared__ float As[2][BK][BM + PAD];   // k-major: As[k][m]
    __shared__ float Bs[2][BK][BN + PAD];   // k-major: Bs[k][n]

    const int tid  = threadIdx.x;
    const int lane = tid & 31;
    const int wid  = tid >> 5;
    const int wm   = wid & 1;       // 0..1  (64 rows each)
    const int wn   = wid >> 1;      // 0..3  (32 cols each)
    const int gid  = lane >> 2;     // 0..7
    const int tig  = lane & 3;      // 0..3

    const int row0 = blockIdx.x * BM;   // M fastest => A tile stays hot in L2
    const int col0 = blockIdx.y * BN;

    float acc[4][4][4];
    #pragma unroll
    for (int i = 0; i < 4; i++)
        #pragma unroll
        for (int j = 0; j < 4; j++)
            #pragma unroll
            for (int z = 0; z < 4; z++) acc[i][j][z] = 0.f;

    // loader thread mappings
    const int arow = tid >> 2;            // 0..63 (A rows, +64 second)
    const int akq  = (tid & 3) * 4;       // k quad
    const int bk_n = tid >> 5;            // 0..7  (NN: B k rows, +8 second)
    const int bn4  = (tid & 31) * 4;      // NN: n quad
    const int bn_t = tid >> 2;            // 0..63 (NT: B n rows, +64 second)
    const int bkq  = (tid & 3) * 4;       // NT: k quad

    float4 pa0, pa1, pb0, pb1;

    #define G_LOAD(k0)                                                              \
        do {                                                                        \
            pa0 = *(const float4*)(A + (size_t)(row0 + arow)      * K + (k0) + akq);\
            pa1 = *(const float4*)(A + (size_t)(row0 + arow + 64) * K + (k0) + akq);\
            if (!TRANSB) {                                                          \
                pb0 = *(const float4*)(Bm + (size_t)((k0) + bk_n)     * N + col0 + bn4); \
                pb1 = *(const float4*)(Bm + (size_t)((k0) + bk_n + 8) * N + col0 + bn4); \
            } else {                                                                \
                pb0 = (col0 + bn_t < N)                                             \
                    ? *(const float4*)(Bm + (size_t)(col0 + bn_t)      * K + (k0) + bkq) \
                    : make_float4(0.f,0.f,0.f,0.f);                                 \
                pb1 = (col0 + bn_t + 64 < N)                                        \
                    ? *(const float4*)(Bm + (size_t)(col0 + bn_t + 64) * K + (k0) + bkq) \
                    : make_float4(0.f,0.f,0.f,0.f);                                 \
            }                                                                       \
        } while (0)

    #define S_STORE(buf)                                                            \
        do {                                                                        \
            As[buf][akq+0][arow]    = to_tf32(pa0.x);                               \
            As[buf][akq+1][arow]    = to_tf32(pa0.y);                               \
            As[buf][akq+2][arow]    = to_tf32(pa0.z);                               \
            As[buf][akq+3][arow]    = to_tf32(pa0.w);                               \
            As[buf][akq+0][arow+64] = to_tf32(pa1.x);                               \
            As[buf][akq+1][arow+64] = to_tf32(pa1.y);                               \
            As[buf][akq+2][arow+64] = to_tf32(pa1.z);                               \
            As[buf][akq+3][arow+64] = to_tf32(pa1.w);                               \
            if (!TRANSB) {                                                          \
                float4 t0 = make_float4(to_tf32(pb0.x), to_tf32(pb0.y),             \
                                        to_tf32(pb0.z), to_tf32(pb0.w));            \
                float4 t1 = make_float4(to_tf32(pb1.x), to_tf32(pb1.y),             \
                                        to_tf32(pb1.z), to_tf32(pb1.w));            \
                *(float4*)&Bs[buf][bk_n  ][bn4] = t0;                               \
                *(float4*)&Bs[buf][bk_n+8][bn4] = t1;                               \
            } else {                                                                \
                Bs[buf][bkq+0][bn_t]    = to_tf32(pb0.x);                           \
                Bs[buf][bkq+1][bn_t]    = to_tf32(pb0.y);                           \
                Bs[buf][bkq+2][bn_t]    = to_tf32(pb0.z);                           \
                Bs[buf][bkq+3][bn_t]    = to_tf32(pb0.w);                           \
                Bs[buf][bkq+0][bn_t+64] = to_tf32(pb1.x);                           \
                Bs[buf][bkq+1][bn_t+64] = to_tf32(pb1.y);                           \
                Bs[buf][bkq+2][bn_t+64] = to_tf32(pb1.z);                           \
                Bs[buf][bkq+3][bn_t+64] = to_tf32(pb1.w);                           \
            }                                                                       \
        } while (0)

    G_LOAD(0);
    S_STORE(0);
    __syncthreads();

    const int ktiles = K / BK;
    for (int t = 0; t < ktiles; t++) {
        const int cur = t & 1;
        if (t + 1 < ktiles) G_LOAD((t + 1) * BK);

        #pragma unroll
        for (int ks = 0; ks < BK; ks += 8) {
            unsigned af[4][4], bf[4][2];
            #pragma unroll
            for (int mi = 0; mi < 4; mi++) {
                int r = wm*64 + mi*16 + gid;
                af[mi][0] = __float_as_uint(As[cur][ks+tig  ][r]);
                af[mi][1] = __float_as_uint(As[cur][ks+tig  ][r+8]);
                af[mi][2] = __float_as_uint(As[cur][ks+tig+4][r]);
                af[mi][3] = __float_as_uint(As[cur][ks+tig+4][r+8]);
            }
            #pragma unroll
            for (int ni = 0; ni < 4; ni++) {
                int c = wn*32 + ni*8 + gid;
                bf[ni][0] = __float_as_uint(Bs[cur][ks+tig  ][c]);
                bf[ni][1] = __float_as_uint(Bs[cur][ks+tig+4][c]);
            }
            #pragma unroll
            for (int mi = 0; mi < 4; mi++)
                #pragma unroll
                for (int ni = 0; ni < 4; ni++)
                    asm volatile(
                        "mma.sync.aligned.m16n8k8.row.col.f32.tf32.tf32.f32 "
                        "{%0,%1,%2,%3}, {%4,%5,%6,%7}, {%8,%9}, {%0,%1,%2,%3};"
                        : "+f"(acc[mi][ni][0]), "+f"(acc[mi][ni][1]),
                          "+f"(acc[mi][ni][2]), "+f"(acc[mi][ni][3])
                        : "r"(af[mi][0]), "r"(af[mi][1]),
                          "r"(af[mi][2]), "r"(af[mi][3]),
                          "r"(bf[ni][0]), "r"(bf[ni][1]));
        }

        if (t + 1 < ktiles) S_STORE(cur ^ 1);
        __syncthreads();
    }
    #undef G_LOAD
    #undef S_STORE

    // epilogue
    #pragma unroll
    for (int mi = 0; mi < 4; mi++) {
        int rbase = row0 + wm*64 + mi*16 + gid;
        #pragma unroll
        for (int ni = 0; ni < 4; ni++) {
            int c = col0 + wn*32 + ni*8 + tig*2;
            #pragma unroll
            for (int hh = 0; hh < 2; hh++) {
                int rr = rbase + hh*8;
                float v0 = acc[mi][ni][hh*2+0];
                float v1 = acc[mi][ni][hh*2+1];
                if (bias) {
                    if (c   < N) v0 += bias[c];
                    if (c+1 < N) v1 += bias[c+1];
                }
                if (act) {
                    v0 = 0.5f * v0 * (1.0f + erff(v0 * 0.70710678118654752f));
                    v1 = 0.5f * v1 * (1.0f + erff(v1 * 0.70710678118654752f));
                }
                if (res) {
                    if (c   < N) v0 += res[(size_t)rr * N + c];
                    if (c+1 < N) v1 += res[(size_t)rr * N + c + 1];
                }
                if (c   < N) C[(size_t)rr * N + c]     = v0;
                if (c+1 < N) C[(size_t)rr * N + c + 1] = v1;
            }
        }
    }
}

// ---------------- fused causal attention ----------------
__global__ void attention_kernel(const float* __restrict__ q,
                                 const float* __restrict__ k,
                                 const float* __restrict__ v,
                                 float* __restrict__ ctx) {
    int i  = blockIdx.x;
    int bh = blockIdx.y;
    int b  = bh / H_, h = bh % H_;
    int t  = threadIdx.x;                   // 128
    __shared__ float sq[HD_];
    __shared__ float sc[S_];
    __shared__ float red[128];

    const float* qrow = q + ((size_t)(b*S_ + i)) * D_ + h * HD_;
    if (t < HD_) sq[t] = qrow[t];
    __syncthreads();

    float lmax = -1e30f;
    for (int j = t; j <= i; j += 128) {
        const float* kr = k + ((size_t)(b*S_ + j)) * D_ + h * HD_;
        float dot = 0.f;
        #pragma unroll
        for (int d = 0; d < HD_; d++) dot = fmaf(sq[d], kr[d], dot);
        dot *= 0.125f;
        sc[j] = dot;
        lmax = fmaxf(lmax, dot);
    }
    red[t] = lmax; __syncthreads();
    #pragma unroll
    for (int o = 64; o > 0; o >>= 1) {
        if (t < o) red[t] = fmaxf(red[t], red[t + o]);
        __syncthreads();
    }
    float m = red[0];
    __syncthreads();

    float lsum = 0.f;
    for (int j = t; j <= i; j += 128) {
        float e = expf(sc[j] - m);
        sc[j] = e;
        lsum += e;
    }
    red[t] = lsum; __syncthreads();
    #pragma unroll
    for (int o = 64; o > 0; o >>= 1) {
        if (t < o) red[t] += red[t + o];
        __syncthreads();
    }
    float rinv = 1.f / red[0];
    __syncthreads();

    if (t < HD_) {
        float acc = 0.f;
        const float* vb = v + (size_t)(b*S_) * D_ + h * HD_ + t;
        for (int j = 0; j <= i; j++)
            acc = fmaf(sc[j], vb[(size_t)j * D_], acc);
        ctx[((size_t)(b*S_ + i)) * D_ + h * HD_ + t] = acc * rinv;
    }
}

// ---------------- loss ----------------
__global__ void loss_kernel(const float* __restrict__ logits,
                            const void* __restrict__ tgt) {
    int n = blockIdx.x;
    const float* row = logits + (size_t)n * V_;
    int t = threadIdx.x;                    // 256
    __shared__ float red[256];
    float m = -1e30f;
    for (int i = t; i < V_; i += 256) m = fmaxf(m, row[i]);
    red[t] = m; __syncthreads();
    #pragma unroll
    for (int o = 128; o > 0; o >>= 1) {
        if (t < o) red[t] = fmaxf(red[t], red[t + o]);
        __syncthreads();
    }
    m = red[0]; __syncthreads();
    float s = 0.f;
    for (int i = t; i < V_; i += 256) s += expf(row[i] - m);
    red[t] = s; __syncthreads();
    #pragma unroll
    for (int o = 128; o > 0; o >>= 1) {
        if (t < o) red[t] += red[t + o];
        __syncthreads();
    }
    if (t == 0) {
        int tg = get_tok(tgt, n);
        g_loss[n] = m + logf(red[0]) - row[tg];
    }
}

__global__ void loss_reduce_kernel(float* __restrict__ out, long long out_size) {
    int t = threadIdx.x;
    __shared__ float red[256];
    float s = 0.f;
    for (int i = t; i < N_TOK; i += 256) s += g_loss[i];
    red[t] = s; __syncthreads();
    #pragma unroll
    for (int o = 128; o > 0; o >>= 1) {
        if (t < o) red[t] += red[t + o];
        __syncthreads();
    }
    if (t == 0) {
        float mean = red[0] / (float)N_TOK;
        if (out_size > NLOGITS)      out[NLOGITS] = mean;
        else if (out_size == 1)      out[0]       = mean;
    }
}

// ---------------- host side ----------------
static void gemm(const float* A, const float* Bm, const float* bias, const float* res,
                 float* C, int M, int N, int K, int act, bool transB) {
    dim3 grid(M / 128, (N + 127) / 128);
    if (transB) mma_gemm_kernel<true ><<<grid, 256>>>(A, Bm, bias, res, C, M, N, K, act);
    else        mma_gemm_kernel<false><<<grid, 256>>>(A, Bm, bias, res, C, M, N, K, act);
}

extern "C" void kernel_launch(void* const* d_in, const int* in_sizes, int n_in,
                              void* d_out, int out_size) {
    const void*  x       = d_in[0];
    const void*  targets = d_in[1];
    const float* temb    = (const float*)d_in[2];
    const float* pemb    = (const float*)d_in[3];
    const float* ln1_g   = (const float*)d_in[4];
    const float* ln1_b   = (const float*)d_in[5];
    const float* Wq      = (const float*)d_in[6];
    const float* bq      = (const float*)d_in[7];
    const float* Wk      = (const float*)d_in[8];
    const float* bk      = (const float*)d_in[9];
    const float* Wv      = (const float*)d_in[10];
    const float* bv      = (const float*)d_in[11];
    const float* Wo      = (const float*)d_in[12];
    const float* bo      = (const float*)d_in[13];
    const float* ln2_g   = (const float*)d_in[14];
    const float* ln2_b   = (const float*)d_in[15];
    const float* W1      = (const float*)d_in[16];
    const float* b1      = (const float*)d_in[17];
    const float* W2      = (const float*)d_in[18];
    const float* b2      = (const float*)d_in[19];
    const float* lnf_g   = (const float*)d_in[20];
    const float* lnf_b   = (const float*)d_in[21];
    float* out = (float*)d_out;

    float *h, *xn, *q, *k, *v, *ctx, *ff;
    cudaGetSymbolAddress((void**)&h,   g_h);
    cudaGetSymbolAddress((void**)&xn,  g_xn);
    cudaGetSymbolAddress((void**)&q,   g_q);
    cudaGetSymbolAddress((void**)&k,   g_k);
    cudaGetSymbolAddress((void**)&v,   g_v);
    cudaGetSymbolAddress((void**)&ctx, g_ctx);
    cudaGetSymbolAddress((void**)&ff,  g_ff);

    detect_kernel<<<1, 256>>>((const int*)x);
    embed_kernel<<<N_TOK, 128>>>(x, temb, pemb);

    for (int l = 0; l < L_; l++) {
        layernorm_kernel<<<N_TOK, 128>>>(h, ln1_g + (size_t)l*D_, ln1_b + (size_t)l*D_, xn);
        gemm(xn, Wq + (size_t)l*D_*D_, bq + (size_t)l*D_, nullptr, q, N_TOK, D_, D_, 0, false);
        gemm(xn, Wk + (size_t)l*D_*D_, bk + (size_t)l*D_, nullptr, k, N_TOK, D_, D_, 0, false);
        gemm(xn, Wv + (size_t)l*D_*D_, bv + (size_t)l*D_, nullptr, v, N_TOK, D_, D_, 0, false);

        dim3 ag(S_, B_ * H_);
        attention_kernel<<<ag, 128>>>(q, k, v, ctx);

        gemm(ctx, Wo + (size_t)l*D_*D_, bo + (size_t)l*D_, h, h, N_TOK, D_, D_, 0, false);

        layernorm_kernel<<<N_TOK, 128>>>(h, ln2_g + (size_t)l*D_, ln2_b + (size_t)l*D_, xn);
        gemm(xn, W1 + (size_t)l*D_*F_, b1 + (size_t)l*F_, nullptr, ff, N_TOK, F_, D_, 1, false);
        gemm(ff, W2 + (size_t)l*F_*D_, b2 + (size_t)l*D_, h, h, N_TOK, D_, F_, 0, false);
    }

    layernorm_kernel<<<N_TOK, 128>>>(h, lnf_g, lnf_b, xn);
    gemm(xn, temb, nullptr, nullptr, out, N_TOK, V_, D_, 0, true);

    loss_kernel<<<N_TOK, 256>>>(out, targets);
    loss_reduce_kernel<<<1, 256>>>(out, (long long)out_size);
}

// round 3
// speedup vs baseline: 5.0101x; 3.4808x over previous
#include <cuda_runtime.h>
#include <math.h>

#define L_  6
#define H_  8
#define D_  512
#define F_  2048
#define S_  512
#define V_  50257
#define B_  8
#define HD_ 64
#define N_TOK (B_*S_)                      // 4096
#define NLOGITS ((long long)N_TOK * V_)    // 205852672
#define QKV3 1536

// ---------------- scratch (static device globals; no allocation) ----------------
__device__ float g_h   [N_TOK*D_];
__device__ float g_xn  [N_TOK*D_];
__device__ float g_qkv [N_TOK*QKV3];
__device__ float g_ctx [N_TOK*D_];
__device__ float g_ff  [N_TOK*F_];
__device__ float g_loss[N_TOK];
__device__ int   g_is64;
// tf32-rounded weight copies
__device__ float g_wqkv [L_*D_*QKV3];
__device__ float g_bqkv [L_*QKV3];
__device__ float g_wo   [L_*D_*D_];
__device__ float g_w1   [L_*D_*F_];
__device__ float g_w2   [L_*F_*D_];
__device__ float g_temb32[(size_t)V_*D_];

__device__ __forceinline__ float to_tf32(float x) {
    float r;
    asm("cvt.rna.tf32.f32 %0, %1;" : "=f"(r) : "f"(x));
    return r;
}

__device__ __forceinline__ void cp_async16(float* smem, const float* gmem, bool pred) {
    unsigned saddr = (unsigned)__cvta_generic_to_shared(smem);
    int sz = pred ? 16 : 0;
    asm volatile("cp.async.cg.shared.global [%0], [%1], 16, %2;\n"
                 :: "r"(saddr), "l"(gmem), "r"(sz));
}
#define CP_COMMIT() asm volatile("cp.async.commit_group;\n")
#define CP_WAIT1()  asm volatile("cp.async.wait_group 1;\n")

// ---------------- int32/int64 token-id detection ----------------
__global__ void detect_kernel(const int* __restrict__ xr) {
    __shared__ int ok;
    if (threadIdx.x == 0) ok = 1;
    __syncthreads();
    for (int i = threadIdx.x; i < N_TOK/2; i += blockDim.x)
        if (xr[2*i + 1] != 0) ok = 0;
    __syncthreads();
    if (threadIdx.x == 0) g_is64 = ok;
}
__device__ __forceinline__ int get_tok(const void* p, int i) {
    return g_is64 ? (int)((const long long*)p)[i] : ((const int*)p)[i];
}

// ---------------- weight prep: tf32 round (+ QKV pack) ----------------
__global__ void cvt_tf32_kernel(const float* __restrict__ src, float* __restrict__ dst, int n4) {
    int i = blockIdx.x * 256 + threadIdx.x;
    if (i < n4) {
        float4 v = ((const float4*)src)[i];
        ((float4*)dst)[i] = make_float4(to_tf32(v.x), to_tf32(v.y), to_tf32(v.z), to_tf32(v.w));
    }
}
__global__ void pack_qkv_kernel(const float* __restrict__ Wq, const float* __restrict__ Wk,
                                const float* __restrict__ Wv) {
    int i = blockIdx.x * 256 + threadIdx.x;      // f4 index over L*D*1536/4
    if (i >= L_*D_*QKV3/4) return;
    int c  = (i % (QKV3/4)) * 4;
    int rest = i / (QKV3/4);
    int d = rest % D_, l = rest / D_;
    const float* src; int off;
    if (c < 512)       { src = Wq; off = c; }
    else if (c < 1024) { src = Wk; off = c - 512; }
    else               { src = Wv; off = c - 1024; }
    float4 v = *(const float4*)&src[((size_t)l*D_ + d)*D_ + off];
    *(float4*)&g_wqkv[((size_t)l*D_ + d)*QKV3 + c] =
        make_float4(to_tf32(v.x), to_tf32(v.y), to_tf32(v.z), to_tf32(v.w));
}
__global__ void pack_bias_kernel(const float* __restrict__ bq, const float* __restrict__ bk,
                                 const float* __restrict__ bv) {
    int i = blockIdx.x * 256 + threadIdx.x;
    if (i >= L_*QKV3) return;
    int l = i / QKV3, c = i % QKV3;
    float v = (c < 512) ? bq[l*512 + c] : (c < 1024) ? bk[l*512 + c - 512] : bv[l*512 + c - 1024];
    g_bqkv[i] = v;
}

// ---------------- embedding ----------------
__global__ void embed_kernel(const void* __restrict__ x,
                             const float* __restrict__ temb,
                             const float* __restrict__ pemb) {
    int n = blockIdx.x;
    int tok = get_tok(x, n);
    int s = n % S_;
    const float4* te = (const float4*)(temb + (size_t)tok * D_);
    const float4* pe = (const float4*)(pemb + (size_t)s   * D_);
    float4* out = (float4*)(g_h + (size_t)n * D_);
    int t = threadIdx.x;
    float4 a = te[t], b = pe[t];
    out[t] = make_float4(a.x+b.x, a.y+b.y, a.z+b.z, a.w+b.w);
}

// ---------------- layernorm (output tf32-rounded: feeds GEMM A) ----------------
__global__ void layernorm_kernel(const float* __restrict__ in,
                                 const float* __restrict__ g,
                                 const float* __restrict__ b,
                                 float* __restrict__ out) {
    int n = blockIdx.x;
    int t = threadIdx.x;
    float4 v = ((const float4*)(in + (size_t)n * D_))[t];
    float s  = v.x + v.y + v.z + v.w;
    float ss = v.x*v.x + v.y*v.y + v.z*v.z + v.w*v.w;
    #pragma unroll
    for (int o = 16; o > 0; o >>= 1) {
        s  += __shfl_down_sync(0xffffffffu, s,  o);
        ss += __shfl_down_sync(0xffffffffu, ss, o);
    }
    __shared__ float rs[4], rss[4];
    __shared__ float mu_s, rstd_s;
    int w = t >> 5, lane = t & 31;
    if (lane == 0) { rs[w] = s; rss[w] = ss; }
    __syncthreads();
    if (t == 0) {
        float S1 = 0.f, S2 = 0.f;
        #pragma unroll
        for (int i = 0; i < 4; i++) { S1 += rs[i]; S2 += rss[i]; }
        float mu = S1 / D_;
        mu_s = mu;
        rstd_s = rsqrtf(S2 / D_ - mu*mu + 1e-5f);
    }
    __syncthreads();
    float mu = mu_s, r = rstd_s;
    float4 gg = ((const float4*)g)[t];
    float4 bb = ((const float4*)b)[t];
    float4 o;
    o.x = to_tf32((v.x - mu) * r * gg.x + bb.x);
    o.y = to_tf32((v.y - mu) * r * gg.y + bb.y);
    o.z = to_tf32((v.z - mu) * r * gg.z + bb.z);
    o.w = to_tf32((v.w - mu) * r * gg.w + bb.w);
    ((float4*)(out + (size_t)n * D_))[t] = o;
}

// ---------------- TF32 tensor-core GEMM, 3-stage cp.async pipeline ----------------
// C[M,N] = epi(A @ B); B [K,N] (NN) or [N,K] (NT). Inputs pre-rounded to tf32.
// 128x128 CTA, BK=32, 8 warps (2m x 4n), warp 64x32, mma m16n8k8.
template<bool TRANSB>
__global__ void __launch_bounds__(256)
mma_gemm_kernel(const float* __restrict__ A, const float* __restrict__ Bm,
                const float* __restrict__ bias, const float* __restrict__ res,
                float* __restrict__ C, int M, int N, int K, int act)
{
    extern __shared__ float sm[];
    float* As = sm;                 // [3][128][36]  (m-major, k contiguous)
    float* Bs = sm + 3*128*36;      // NN: [3][32][136] ; NT: [3][128][36]

    const int tid  = threadIdx.x;
    const int lane = tid & 31, wid = tid >> 5;
    const int wm = wid & 1, wn = wid >> 1;
    const int gid = lane >> 2, tig = lane & 3;
    const int row0 = blockIdx.x * 128;
    const int col0 = blockIdx.y * 128;

    float acc[4][4][4];
    #pragma unroll
    for (int i = 0; i < 4; i++)
        #pragma unroll
        for (int j = 0; j < 4; j++)
            #pragma unroll
            for (int z = 0; z < 4; z++) acc[i][j][z] = 0.f;

    const int kt = K >> 5;

    auto load_tile = [&](int t, int st) {
        int k0 = t << 5;
        float* as = As + st*128*36;
        #pragma unroll
        for (int i = 0; i < 4; i++) {
            int idx = tid + (i << 8);
            int r = idx >> 3, kq = (idx & 7) << 2;
            cp_async16(as + r*36 + kq, A + (size_t)(row0 + r)*K + k0 + kq, true);
        }
        if (!TRANSB) {
            float* bs = Bs + st*32*136;
            #pragma unroll
            for (int i = 0; i < 4; i++) {
                int idx = tid + (i << 8);
                int kr = idx >> 5, nq = (idx & 31) << 2;
                cp_async16(bs + kr*136 + nq, Bm + (size_t)(k0 + kr)*N + col0 + nq, true);
            }
        } else {
            float* bs = Bs + st*128*36;
            #pragma unroll
            for (int i = 0; i < 4; i++) {
                int idx = tid + (i << 8);
                int r = idx >> 3, kq = (idx & 7) << 2;
                cp_async16(bs + r*36 + kq, Bm + (size_t)(col0 + r)*K + k0 + kq, col0 + r < N);
            }
        }
    };

    load_tile(0, 0); CP_COMMIT();
    if (kt > 1) load_tile(1, 1);
    CP_COMMIT();

    for (int t = 0; t < kt; t++) {
        CP_WAIT1();
        __syncthreads();
        const int st = t % 3;
        if (t + 2 < kt) load_tile(t + 2, (t + 2) % 3);
        CP_COMMIT();

        const float* as = As + st*128*36;
        const float* bs = (!TRANSB) ? (Bs + st*32*136) : (Bs + st*128*36);
        #pragma unroll
        for (int ks = 0; ks < 32; ks += 8) {
            unsigned af[4][4], bf[4][2];
            #pragma unroll
            for (int mi = 0; mi < 4; mi++) {
                int r = wm*64 + mi*16 + gid;
                af[mi][0] = __float_as_uint(as[(size_t)r*36 + ks + tig]);
                af[mi][1] = __float_as_uint(as[(size_t)(r + 8)*36 + ks + tig]);
                af[mi][2] = __float_as_uint(as[(size_t)r*36 + ks + tig + 4]);
                af[mi][3] = __float_as_uint(as[(size_t)(r + 8)*36 + ks + tig + 4]);
            }
            #pragma unroll
            for (int ni = 0; ni < 4; ni++) {
                int c = wn*32 + ni*8 + gid;
                if (!TRANSB) {
                    bf[ni][0] = __float_as_uint(bs[(size_t)(ks + tig)*136 + c]);
                    bf[ni][1] = __float_as_uint(bs[(size_t)(ks + tig + 4)*136 + c]);
                } else {
                    bf[ni][0] = __float_as_uint(bs[(size_t)c*36 + ks + tig]);
                    bf[ni][1] = __float_as_uint(bs[(size_t)c*36 + ks + tig + 4]);
                }
            }
            #pragma unroll
            for (int mi = 0; mi < 4; mi++)
                #pragma unroll
                for (int ni = 0; ni < 4; ni++)
                    asm volatile(
                        "mma.sync.aligned.m16n8k8.row.col.f32.tf32.tf32.f32 "
                        "{%0,%1,%2,%3}, {%4,%5,%6,%7}, {%8,%9}, {%0,%1,%2,%3};"
                        : "+f"(acc[mi][ni][0]), "+f"(acc[mi][ni][1]),
                          "+f"(acc[mi][ni][2]), "+f"(acc[mi][ni][3])
                        : "r"(af[mi][0]), "r"(af[mi][1]),
                          "r"(af[mi][2]), "r"(af[mi][3]),
                          "r"(bf[ni][0]), "r"(bf[ni][1]));
        }
    }

    // epilogue
    #pragma unroll
    for (int mi = 0; mi < 4; mi++) {
        int rbase = row0 + wm*64 + mi*16 + gid;
        #pragma unroll
        for (int ni = 0; ni < 4; ni++) {
            int c = col0 + wn*32 + ni*8 + tig*2;
            #pragma unroll
            for (int hh = 0; hh < 2; hh++) {
                int rr = rbase + hh*8;
                float v0 = acc[mi][ni][hh*2+0];
                float v1 = acc[mi][ni][hh*2+1];
                if (bias) {
                    if (c   < N) v0 += bias[c];
                    if (c+1 < N) v1 += bias[c+1];
                }
                if (act) {
                    v0 = to_tf32(0.5f * v0 * (1.0f + erff(v0 * 0.70710678118654752f)));
                    v1 = to_tf32(0.5f * v1 * (1.0f + erff(v1 * 0.70710678118654752f)));
                }
                if (res) {
                    if (c   < N) v0 += res[(size_t)rr * N + c];
                    if (c+1 < N) v1 += res[(size_t)rr * N + c + 1];
                }
                if (c   < N) C[(size_t)rr * N + c]     = v0;
                if (c+1 < N) C[(size_t)rr * N + c + 1] = v1;
            }
        }
    }
}

// ---------------- flash attention (fp32, 64-q tile, online softmax) ----------------
// grid (8 qtiles, 64 bh), 256 threads = 16x16; thread owns 4x4 of the 64x64 tile.
__global__ void __launch_bounds__(256)
flash_kernel(const float* __restrict__ qkv, float* __restrict__ ctx) {
    extern __shared__ float sm[];
    float* Qs = sm;                 // [64][68]
    float* Ks = sm + 64*68;
    float* Vs = sm + 2*64*68;
    float* Ps = sm + 3*64*68;

    const int it = blockIdx.x, bh = blockIdx.y;
    const int b = bh >> 3, h = bh & 7;
    const int tid = threadIdx.x;
    const int ty = tid >> 4, tx = tid & 15;
    const size_t base = (size_t)(b * S_) * QKV3 + h * HD_;

    #pragma unroll
    for (int i = 0; i < 4; i++) {
        int idx = tid + (i << 8);
        int r = idx >> 4, cq = (idx & 15) << 2;
        *(float4*)&Qs[r*68 + cq] = *(const float4*)&qkv[base + (size_t)(it*64 + r)*QKV3 + cq];
    }

    float O[4][4], mr[4], lr[4];
    #pragma unroll
    for (int i = 0; i < 4; i++) {
        mr[i] = -1e30f; lr[i] = 0.f;
        #pragma unroll
        for (int j = 0; j < 4; j++) O[i][j] = 0.f;
    }

    for (int jt = 0; jt <= it; jt++) {
        __syncthreads();
        #pragma unroll
        for (int i = 0; i < 4; i++) {
            int idx = tid + (i << 8);
            int r = idx >> 4, cq = (idx & 15) << 2;
            size_t g = base + (size_t)(jt*64 + r)*QKV3 + cq;
            *(float4*)&Ks[r*68 + cq] = *(const float4*)&qkv[g + 512];
            *(float4*)&Vs[r*68 + cq] = *(const float4*)&qkv[g + 1024];
        }
        __syncthreads();

        float S[4][4];
        #pragma unroll
        for (int i = 0; i < 4; i++)
            #pragma unroll
            for (int j = 0; j < 4; j++) S[i][j] = 0.f;

        #pragma unroll 4
        for (int kk = 0; kk < 64; kk += 4) {
            float4 qa[4], kb[4];
            #pragma unroll
            for (int i = 0; i < 4; i++) qa[i] = *(const float4*)&Qs[(ty*4 + i)*68 + kk];
            #pragma unroll
            for (int j = 0; j < 4; j++) kb[j] = *(const float4*)&Ks[(tx*4 + j)*68 + kk];
            #pragma unroll
            for (int i = 0; i < 4; i++)
                #pragma unroll
                for (int j = 0; j < 4; j++)
                    S[i][j] += qa[i].x*kb[j].x + qa[i].y*kb[j].y
                             + qa[i].z*kb[j].z + qa[i].w*kb[j].w;
        }

        const bool diag = (jt == it);
        #pragma unroll
        for (int i = 0; i < 4; i++) {
            int row = ty*4 + i;
            #pragma unroll
            for (int j = 0; j < 4; j++) {
                float s = S[i][j] * 0.125f;
                if (diag && (tx*4 + j) > row) s = -1e30f;
                S[i][j] = s;
            }
            float tmax = fmaxf(fmaxf(S[i][0], S[i][1]), fmaxf(S[i][2], S[i][3]));
            #pragma unroll
            for (int o = 1; o < 16; o <<= 1)
                tmax = fmaxf(tmax, __shfl_xor_sync(0xffffffffu, tmax, o));
            float mnew = fmaxf(mr[i], tmax);
            float p0 = __expf(S[i][0] - mnew), p1 = __expf(S[i][1] - mnew);
            float p2 = __expf(S[i][2] - mnew), p3 = __expf(S[i][3] - mnew);
            float rsum = p0 + p1 + p2 + p3;
            #pragma unroll
            for (int o = 1; o < 16; o <<= 1)
                rsum += __shfl_xor_sync(0xffffffffu, rsum, o);
            float scale = __expf(mr[i] - mnew);
            lr[i] = lr[i]*scale + rsum;
            mr[i] = mnew;
            #pragma unroll
            for (int j = 0; j < 4; j++) O[i][j] *= scale;
            *(float4*)&Ps[row*68 + tx*4] = make_float4(p0, p1, p2, p3);
        }
        __syncthreads();

        #pragma unroll 4
        for (int kk = 0; kk < 64; kk += 4) {
            float vv[4][4];
            #pragma unroll
            for (int c = 0; c < 4; c++) {
                float4 v4 = *(const float4*)&Vs[(kk + c)*68 + tx*4];
                vv[c][0] = v4.x; vv[c][1] = v4.y; vv[c][2] = v4.z; vv[c][3] = v4.w;
            }
            #pragma unroll
            for (int i = 0; i < 4; i++) {
                float4 p = *(const float4*)&Ps[(ty*4 + i)*68 + kk];
                #pragma unroll
                for (int j = 0; j < 4; j++)
                    O[i][j] += p.x*vv[0][j] + p.y*vv[1][j] + p.z*vv[2][j] + p.w*vv[3][j];
            }
        }
    }

    #pragma unroll
    for (int i = 0; i < 4; i++) {
        int row = it*64 + ty*4 + i;
        float inv = 1.f / lr[i];
        float4 o = make_float4(to_tf32(O[i][0]*inv), to_tf32(O[i][1]*inv),
                               to_tf32(O[i][2]*inv), to_tf32(O[i][3]*inv));
        *(float4*)&ctx[(size_t)(b*S_ + row)*D_ + h*HD_ + tx*4] = o;
    }
}

// ---------------- loss ----------------
__global__ void loss_kernel(const float* __restrict__ logits,
                            const void* __restrict__ tgt) {
    int n = blockIdx.x;
    const float* row = logits + (size_t)n * V_;
    int t = threadIdx.x;
    __shared__ float red[256];
    float m = -1e30f;
    for (int i = t; i < V_; i += 256) m = fmaxf(m, row[i]);
    red[t] = m; __syncthreads();
    #pragma unroll
    for (int o = 128; o > 0; o >>= 1) {
        if (t < o) red[t] = fmaxf(red[t], red[t + o]);
        __syncthreads();
    }
    m = red[0]; __syncthreads();
    float s = 0.f;
    for (int i = t; i < V_; i += 256) s += __expf(row[i] - m);
    red[t] = s; __syncthreads();
    #pragma unroll
    for (int o = 128; o > 0; o >>= 1) {
        if (t < o) red[t] += red[t + o];
        __syncthreads();
    }
    if (t == 0) {
        int tg = get_tok(tgt, n);
        g_loss[n] = m + logf(red[0]) - row[tg];
    }
}

__global__ void loss_reduce_kernel(float* __restrict__ out, long long out_size) {
    int t = threadIdx.x;
    __shared__ float red[256];
    float s = 0.f;
    for (int i = t; i < N_TOK; i += 256) s += g_loss[i];
    red[t] = s; __syncthreads();
    #pragma unroll
    for (int o = 128; o > 0; o >>= 1) {
        if (t < o) red[t] += red[t + o];
        __syncthreads();
    }
    if (t == 0) {
        float mean = red[0] / (float)N_TOK;
        if (out_size > NLOGITS)      out[NLOGITS] = mean;
        else if (out_size == 1)      out[0]       = mean;
    }
}

// ---------------- host side ----------------
#define GEMM_SMEM (3*128*36*4 + 3*128*36*4)   // 110592 B (covers NN/NT variants)
#define FLASH_SMEM (4*64*68*4)                // 69632 B

static void gemm(const float* A, const float* Bm, const float* bias, const float* res,
                 float* C, int M, int N, int K, int act, bool transB) {
    dim3 grid(M / 128, (N + 127) / 128);
    if (transB) {
        cudaFuncSetAttribute(mma_gemm_kernel<true>,  cudaFuncAttributeMaxDynamicSharedMemorySize, GEMM_SMEM);
        mma_gemm_kernel<true ><<<grid, 256, GEMM_SMEM>>>(A, Bm, bias, res, C, M, N, K, act);
    } else {
        cudaFuncSetAttribute(mma_gemm_kernel<false>, cudaFuncAttributeMaxDynamicSharedMemorySize, GEMM_SMEM);
        mma_gemm_kernel<false><<<grid, 256, GEMM_SMEM>>>(A, Bm, bias, res, C, M, N, K, act);
    }
}

extern "C" void kernel_launch(void* const* d_in, const int* in_sizes, int n_in,
                              void* d_out, int out_size) {
    const void*  x       = d_in[0];
    const void*  targets = d_in[1];
    const float* temb    = (const float*)d_in[2];
    const float* pemb    = (const float*)d_in[3];
    const float* ln1_g   = (const float*)d_in[4];
    const float* ln1_b   = (const float*)d_in[5];
    const float* Wq      = (const float*)d_in[6];
    const float* bq      = (const float*)d_in[7];
    const float* Wk      = (const float*)d_in[8];
    const float* bk      = (const float*)d_in[9];
    const float* Wv      = (const float*)d_in[10];
    const float* bv      = (const float*)d_in[11];
    const float* Wo      = (const float*)d_in[12];
    const float* bo      = (const float*)d_in[13];
    const float* ln2_g   = (const float*)d_in[14];
    const float* ln2_b   = (const float*)d_in[15];
    const float* W1      = (const float*)d_in[16];
    const float* b1      = (const float*)d_in[17];
    const float* W2      = (const float*)d_in[18];
    const float* b2      = (const float*)d_in[19];
    const float* lnf_g   = (const float*)d_in[20];
    const float* lnf_b   = (const float*)d_in[21];
    float* out = (float*)d_out;

    float *h, *xn, *qkv, *ctx, *ff;
    float *wqkv, *bqkv, *wo, *w1, *w2, *temb32;
    cudaGetSymbolAddress((void**)&h,    g_h);
    cudaGetSymbolAddress((void**)&xn,   g_xn);
    cudaGetSymbolAddress((void**)&qkv,  g_qkv);
    cudaGetSymbolAddress((void**)&ctx,  g_ctx);
    cudaGetSymbolAddress((void**)&ff,   g_ff);
    cudaGetSymbolAddress((void**)&wqkv, g_wqkv);
    cudaGetSymbolAddress((void**)&bqkv, g_bqkv);
    cudaGetSymbolAddress((void**)&wo,   g_wo);
    cudaGetSymbolAddress((void**)&w1,   g_w1);
    cudaGetSymbolAddress((void**)&w2,   g_w2);
    cudaGetSymbolAddress((void**)&temb32, g_temb32);

    cudaFuncSetAttribute(flash_kernel, cudaFuncAttributeMaxDynamicSharedMemorySize, FLASH_SMEM);

    detect_kernel<<<1, 256>>>((const int*)x);

    // weight prep (tf32 rounding / packing)
    {
        int n4;
        n4 = L_*D_*QKV3/4;  pack_qkv_kernel<<<(n4 + 255)/256, 256>>>(Wq, Wk, Wv);
        pack_bias_kernel<<<(L_*QKV3 + 255)/256, 256>>>(bq, bk, bv);
        n4 = L_*D_*D_/4;    cvt_tf32_kernel<<<(n4 + 255)/256, 256>>>(Wo, wo, n4);
        n4 = L_*D_*F_/4;    cvt_tf32_kernel<<<(n4 + 255)/256, 256>>>(W1, w1, n4);
        n4 = L_*F_*D_/4;    cvt_tf32_kernel<<<(n4 + 255)/256, 256>>>(W2, w2, n4);
        long long nt4 = (long long)V_*D_/4;
        cvt_tf32_kernel<<<(int)((nt4 + 255)/256), 256>>>(temb, temb32, (int)nt4);
    }

    embed_kernel<<<N_TOK, 128>>>(x, temb, pemb);

    for (int l = 0; l < L_; l++) {
        layernorm_kernel<<<N_TOK, 128>>>(h, ln1_g + (size_t)l*D_, ln1_b + (size_t)l*D_, xn);
        gemm(xn, wqkv + (size_t)l*D_*QKV3, bqkv + (size_t)l*QKV3, nullptr,
             qkv, N_TOK, QKV3, D_, 0, false);

        flash_kernel<<<dim3(8, B_*H_), 256, FLASH_SMEM>>>(qkv, ctx);

        gemm(ctx, wo + (size_t)l*D_*D_, bo + (size_t)l*D_, h, h, N_TOK, D_, D_, 0, false);

        layernorm_kernel<<<N_TOK, 128>>>(h, ln2_g + (size_t)l*D_, ln2_b + (size_t)l*D_, xn);
        gemm(xn, w1 + (size_t)l*D_*F_, b1 + (size_t)l*F_, nullptr, ff, N_TOK, F_, D_, 1, false);
        gemm(ff, w2 + (size_t)l*F_*D_, b2 + (size_t)l*D_, h, h, N_TOK, D_, F_, 0, false);
    }

    layernorm_kernel<<<N_TOK, 128>>>(h, lnf_g, lnf_b, xn);
    gemm(xn, temb32, nullptr, nullptr, out, N_TOK, V_, D_, 0, true);

    loss_kernel<<<N_TOK, 256>>>(out, targets);
    loss_reduce_kernel<<<1, 256>>>(out, (long long)out_size);
}